// round 3
// baseline (speedup 1.0000x reference)
#include <cuda_runtime.h>
#include <math.h>
#include <stdint.h>

// ---------------- problem constants ----------------
#define T_STEPS 512
#define BATCH   64
#define HID     512
#define VOCAB   10000
#define TH      1536          // 3*H
#define NSTK    2
#define SDEP    32
#define EDIM    64
#define JTOT    1670          // 1536 + 6 + 128 fused output cols
#define JPAD    1680          // 105 * 16
#define NBLK    105
#define NTHR    256
#define NTOT    (NBLK*NTHR)   // 26880
#define GATE_ELEMS (BATCH*HID)            // 32768
#define STK_ELEMS  (BATCH*NSTK*SDEP*EDIM) // 262144

// ---------------- scratch (device globals; no allocation allowed) ----------
__device__ float g_EmbW[VOCAB*TH];          // emb @ W_ih^T + b_ih  (61.4 MB)
__device__ float g_hbh[2][BATCH*HID];       // h, [b][i]
__device__ float g_hT [2][HID*BATCH];       // h, [i][b]
__device__ float g_Gact[BATCH*JPAD];        // fused pre-activations, [b][j]
__device__ float g_st[2][STK_ELEMS];        // stacks double buffer
__device__ unsigned g_bar;                  // grid barrier counter

typedef unsigned long long u64;

// ---------------- f32x2 helpers (Blackwell packed fp32) ----------------
__device__ __forceinline__ u64 pack2(float x, float y){
    u64 r; asm("mov.b64 %0, {%1,%2};" : "=l"(r) : "f"(x), "f"(y)); return r;
}
__device__ __forceinline__ void unpack2(u64 v, float &x, float &y){
    asm("mov.b64 {%0,%1}, %2;" : "=f"(x), "=f"(y) : "l"(v));
}
__device__ __forceinline__ void fmax2(u64 &d, u64 a, u64 b){
    asm("fma.rn.f32x2 %0, %1, %2, %0;" : "+l"(d) : "l"(a), "l"(b));
}
// 128-bit shared load as a PLAIN C++ load (compiler emits ld.shared.v2.u64 and
// respects __syncthreads ordering — the previous inline-asm version was CSE'd
// across barriers, which corrupted EmbW).
__device__ __forceinline__ void lds_v2(u64 &a, u64 &b, const void* p){
    ulonglong2 v = *(const ulonglong2*)p;
    a = v.x; b = v.y;
}

__device__ __forceinline__ float sigf(float x){
    return __fdividef(1.f, 1.f + __expf(-x));
}

// ---------------- init: state buffers + barrier reset ----------------
__global__ void init_kernel(const float* __restrict__ hidden,
                            const float* __restrict__ stacks){
    int i = blockIdx.x*blockDim.x + threadIdx.x;
    int stride = gridDim.x*blockDim.x;
    if (i == 0) g_bar = 0u;
    for (int u = i; u < BATCH*HID; u += stride){
        float v = hidden[u];
        g_hbh[0][u] = v;
        int b = u >> 9, h = u & 511;
        g_hT[0][h*BATCH + b] = v;
    }
    for (int u = i; u < STK_ELEMS; u += stride)
        g_st[0][u] = stacks[u];
}

// ---------------- EmbW = emb @ W_ih^T + b_ih  (V x 1536, K=512) ----------
#define GBM 64
#define GBN 64
#define GBK 16
__global__ void __launch_bounds__(256) embw_kernel(const float* __restrict__ emb,
                                                   const float* __restrict__ Wih,
                                                   const float* __restrict__ bih){
    __shared__ __align__(16) float As[GBK][68];
    __shared__ __align__(16) float Bs[GBK][68];
    int tid = threadIdx.x;
    int bm = blockIdx.x*GBM, bn = blockIdx.y*GBN;
    int tx = tid & 15, ty = tid >> 4;
    int lm = tid >> 2, lk = (tid & 3) * 4;

    u64 acc[4][2];
#pragma unroll
    for (int i = 0; i < 4; i++){ acc[i][0] = 0ull; acc[i][1] = 0ull; }

    bool aok = (bm + lm) < VOCAB;
    const float* arow = emb + (size_t)(bm + lm)*HID + lk;
    const float* brow = Wih + (size_t)(bn + lm)*HID + lk;

    for (int kt = 0; kt < HID; kt += GBK){
        float4 av = aok ? *(const float4*)(arow + kt) : make_float4(0.f,0.f,0.f,0.f);
        float4 bv = *(const float4*)(brow + kt);
        __syncthreads();
        As[lk+0][lm]=av.x; As[lk+1][lm]=av.y; As[lk+2][lm]=av.z; As[lk+3][lm]=av.w;
        Bs[lk+0][lm]=bv.x; Bs[lk+1][lm]=bv.y; Bs[lk+2][lm]=bv.z; Bs[lk+3][lm]=bv.w;
        __syncthreads();
#pragma unroll
        for (int k = 0; k < GBK; k++){
            float4 a = *(const float4*)&As[k][ty*4];
            u64 b01, b23; lds_v2(b01, b23, &Bs[k][tx*4]);
            u64 s;
            s = pack2(a.x,a.x); fmax2(acc[0][0],s,b01); fmax2(acc[0][1],s,b23);
            s = pack2(a.y,a.y); fmax2(acc[1][0],s,b01); fmax2(acc[1][1],s,b23);
            s = pack2(a.z,a.z); fmax2(acc[2][0],s,b01); fmax2(acc[2][1],s,b23);
            s = pack2(a.w,a.w); fmax2(acc[3][0],s,b01); fmax2(acc[3][1],s,b23);
        }
    }
    int n0 = bn + tx*4;
    float bv0 = bih[n0+0], bv1 = bih[n0+1], bv2 = bih[n0+2], bv3 = bih[n0+3];
#pragma unroll
    for (int i = 0; i < 4; i++){
        int m = bm + ty*4 + i;
        if (m < VOCAB){
            float c0,c1,c2,c3;
            unpack2(acc[i][0], c0, c1); unpack2(acc[i][1], c2, c3);
            float4 res = make_float4(c0+bv0, c1+bv1, c2+bv2, c3+bv3);
            *(float4*)&g_EmbW[(size_t)m*TH + n0] = res;
        }
    }
}

// ---------------- grid barrier (all 105 blocks co-resident) ---------------
__device__ __forceinline__ void gridsync(unsigned &target){
    __syncthreads();
    target += NBLK;
    if (threadIdx.x == 0){
        __threadfence();
        atomicAdd(&g_bar, 1u);
        unsigned v;
        do {
            asm volatile("ld.volatile.global.u32 %0, [%1];" : "=r"(v) : "l"(&g_bar));
        } while (v < target);
        __threadfence();
    }
    __syncthreads();
}

// ---------------- persistent recurrence kernel ----------------------------
// dyn smem: Wsh float[512*16] (32KB) + Hsh u64[4096] (32KB) = 64KB
#define RNN_SMEM (512*16*4 + 4096*8)

__global__ void __launch_bounds__(NTHR, 1) rnn_kernel(
    const int*   __restrict__ tokens,
    const float* __restrict__ Whh,  const float* __restrict__ Wact,
    const float* __restrict__ Wstk, const float* __restrict__ bhh,
    const float* __restrict__ bact, const float* __restrict__ bstk,
    const float* __restrict__ empty_e,
    float* __restrict__ out)
{
    extern __shared__ __align__(16) char smem[];
    float* Wsh = (float*)smem;                    // [k(512)][16 cols]
    u64*   Hsh = (u64*)(smem + 512*16*4);         // [kk(64)][b(64)] splatted

    const int tid = threadIdx.x, blk = blockIdx.x;
    const int b   = tid & 63, g = tid >> 6;       // g in 0..3, 4 cols each
    const int j0  = blk * 16;
    const int gtid = blk*NTHR + tid;

    // load this block's 16 weight columns into shared (persists all steps)
    for (int idx = tid; idx < 512*16; idx += NTHR){
        int k = idx >> 4, jl = idx & 15;
        int j = j0 + jl;
        float w = 0.f;
        if      (j < TH)     w = Whh [(size_t)j*HID + k];
        else if (j < TH+6)   w = Wact[(size_t)(j-TH)*HID + k];
        else if (j < JTOT)   w = Wstk[(size_t)(j-TH-6)*HID + k];
        Wsh[k*16 + jl] = w;
    }
    float bias[4];
#pragma unroll
    for (int m = 0; m < 4; m++){
        int j = j0 + g*4 + m;
        float bv = 0.f;
        if      (j < TH)   bv = bhh [j];
        else if (j < TH+6) bv = bact[j-TH];
        else if (j < JTOT) bv = bstk[j-TH-6];
        bias[m] = bv;
    }

    float* outputs = out;
    float* out_h   = out + (size_t)T_STEPS*BATCH*HID;
    float* out_st  = out_h + BATCH*HID;

    unsigned target = 0;

    for (int t = 0; t < T_STEPS; t++){
        const int cur = t & 1, nxt = cur ^ 1;

        // ============ Stage A: Gact[b][j] = h_old . Wf[j] + bias =========
        const float4* hT4 = (const float4*)g_hT[cur];
        u64 acc01 = 0ull, acc23 = 0ull;
        float4 pre[4];
#pragma unroll
        for (int r = 0; r < 4; r++) pre[r] = __ldcg(hT4 + tid + 256*r);

        for (int kc = 0; kc < 8; kc++){
            __syncthreads();
#pragma unroll
            for (int r = 0; r < 4; r++){
                int base = (tid + 256*r) * 4;
                Hsh[base+0] = pack2(pre[r].x, pre[r].x);
                Hsh[base+1] = pack2(pre[r].y, pre[r].y);
                Hsh[base+2] = pack2(pre[r].z, pre[r].z);
                Hsh[base+3] = pack2(pre[r].w, pre[r].w);
            }
            __syncthreads();
            if (kc < 7){
#pragma unroll
                for (int r = 0; r < 4; r++)
                    pre[r] = __ldcg(hT4 + (kc+1)*1024 + tid + 256*r);
            }
            const u64*   hp = Hsh + b;
            const float* wp = Wsh + (kc*64)*16 + g*4;
#pragma unroll
            for (int kk = 0; kk < 64; kk++){
                u64 h2 = hp[kk*64];
                u64 w01, w23; lds_v2(w01, w23, wp + kk*16);
                fmax2(acc01, h2, w01);
                fmax2(acc23, h2, w23);
            }
        }
        {
            float a0,a1,a2,a3;
            unpack2(acc01, a0, a1); unpack2(acc23, a2, a3);
            float4 res = make_float4(a0+bias[0], a1+bias[1], a2+bias[2], a3+bias[3]);
            *(float4*)&g_Gact[b*JPAD + j0 + g*4] = res;
        }

        gridsync(target);

        // ============ Stage B: gates + stack update ======================
        const int* tok_t = tokens + t*BATCH;
        for (int u = gtid; u < GATE_ELEMS + STK_ELEMS; u += NTOT){
            if (u < GATE_ELEMS){
                int bb = u >> 9, i = u & 511;
                int tk = __ldg(tok_t + bb);
                const float* gi = g_EmbW + (size_t)tk*TH + i;
                float gir = gi[0], giz = gi[512], gin = gi[1024];
                const float* gh = g_Gact + bb*JPAD + i;
                float ghr = __ldcg(gh), ghz = __ldcg(gh+512), ghn = __ldcg(gh+1024);
                float hold = __ldcg(&g_hbh[cur][u]);
                float r = sigf(gir + ghr);
                float z = sigf(giz + ghz);
                float n = tanhf(gin + r*ghn);
                float nh = (1.f - z)*n + z*hold;
                outputs[(size_t)t*GATE_ELEMS + u] = nh;
                g_hbh[nxt][u] = nh;
                g_hT [nxt][i*BATCH + bb] = nh;
                if (t == T_STEPS-1) out_h[u] = nh;
            } else {
                int u2 = u - GATE_ELEMS;
                int e  = u2 & 63;
                int i  = (u2 >> 6) & 31;
                int nn = (u2 >> 11) & 1;
                int bb = u2 >> 12;
                const float* ga = g_Gact + bb*JPAD + TH + nn*3;
                float l0 = __ldcg(ga), l1 = __ldcg(ga+1), l2 = __ldcg(ga+2);
                float mx = fmaxf(l0, fmaxf(l1, l2));
                float e0 = __expf(l0-mx), e1 = __expf(l1-mx), e2 = __expf(l2-mx);
                float inv = __fdividef(1.f, e0+e1+e2);
                float p0 = e0*inv, p1 = e1*inv, p2 = e2*inv;
                float val;
                if (i == 0){
                    float pv = tanhf(__ldcg(&g_Gact[bb*JPAD + TH + 6 + nn*EDIM + e]));
                    val = p0 * pv;
                } else if (i == SDEP-1){
                    val = __ldg(empty_e + e);
                } else {
                    const float* sc = g_st[cur] + u2;
                    val = p0*__ldcg(sc - EDIM) + p1*__ldcg(sc + EDIM) + p2*__ldcg(sc);
                }
                g_st[nxt][u2] = val;
                if (t == T_STEPS-1) out_st[u2] = val;
            }
        }

        gridsync(target);
    }
}

// ---------------- launch --------------------------------------------------
extern "C" void kernel_launch(void* const* d_in, const int* in_sizes, int n_in,
                              void* d_out, int out_size){
    const int*   tokens  = (const int*)  d_in[0];
    const float* hidden  = (const float*)d_in[1];
    const float* stacks  = (const float*)d_in[2];
    const float* emb     = (const float*)d_in[3];
    const float* Wih     = (const float*)d_in[4];
    const float* Whh     = (const float*)d_in[5];
    const float* bih     = (const float*)d_in[6];
    const float* bhh     = (const float*)d_in[7];
    const float* Wact    = (const float*)d_in[8];
    const float* bact    = (const float*)d_in[9];
    const float* Wstk    = (const float*)d_in[10];
    const float* bstk    = (const float*)d_in[11];
    const float* empty_e = (const float*)d_in[12];
    float* out = (float*)d_out;

    init_kernel<<<128, 256>>>(hidden, stacks);

    dim3 ggrid((VOCAB + GBM - 1)/GBM, TH/GBN);   // 157 x 24
    embw_kernel<<<ggrid, 256>>>(emb, Wih, bih);

    cudaFuncSetAttribute(rnn_kernel, cudaFuncAttributeMaxDynamicSharedMemorySize, RNN_SMEM);
    rnn_kernel<<<NBLK, NTHR, RNN_SMEM>>>(tokens, Whh, Wact, Wstk,
                                         bhh, bact, bstk, empty_e, out);
}

// round 5
// speedup vs baseline: 1.3985x; 1.3985x over previous
#include <cuda_runtime.h>
#include <math.h>
#include <stdint.h>

// ---------------- problem constants ----------------
#define T_STEPS 512
#define BATCH   64
#define HID     512
#define VOCAB   10000
#define TH      1536          // 3*H
#define ACT_OFF 1536          // 6 softmax logits (2 stacks x 3)
#define PUSH_OFF 1544         // push values (128), padded for float4 align
#define JTOT    1672
#define JPAD    1680          // 105 * 16
#define NSTK    2
#define SDEP    32
#define EDIM    64
#define NBLK    105
#define NTHR    256
#define NTOT    (NBLK*NTHR)   // 26880
#define GATE_ELEMS (BATCH*HID)            // 32768
#define STK_ELEMS  (BATCH*NSTK*SDEP*EDIM) // 262144
#define GATE4 (GATE_ELEMS/4)              // 8192
#define STK4  (STK_ELEMS/4)               // 65536

// ---------------- scratch (device globals) ----------------
__device__ float g_EmbW[VOCAB*TH];          // emb @ W_ih^T + b_ih
__device__ float g_hbh[2][BATCH*HID];       // h, [b][i]
__device__ float g_hT [2][HID*BATCH];       // h, [i][b]
__device__ float g_Gact[BATCH*JPAD];        // fused pre-activations, [b][j]
__device__ float g_st[2][STK_ELEMS];        // stacks double buffer
__device__ unsigned g_bar;                  // grid barrier counter

typedef unsigned long long u64;

__device__ __forceinline__ u64 pack2(float x, float y){
    u64 r; asm("mov.b64 %0, {%1,%2};" : "=l"(r) : "f"(x), "f"(y)); return r;
}
__device__ __forceinline__ void unpack2(u64 v, float &x, float &y){
    asm("mov.b64 {%0,%1}, %2;" : "=f"(x), "=f"(y) : "l"(v));
}
__device__ __forceinline__ void fmax2(u64 &d, u64 a, u64 b){
    asm("fma.rn.f32x2 %0, %1, %2, %0;" : "+l"(d) : "l"(a), "l"(b));
}
__device__ __forceinline__ float sigf(float x){
    return __fdividef(1.f, 1.f + __expf(-x));
}
__device__ __forceinline__ void barsync(int id, int cnt){
    asm volatile("bar.sync %0, %1;" :: "r"(id), "r"(cnt) : "memory");
}
__device__ __forceinline__ void bararrive(int id, int cnt){
    asm volatile("bar.arrive %0, %1;" :: "r"(id), "r"(cnt) : "memory");
}

// ---------------- EmbW = emb @ W_ih^T + b_ih  (+ merged init) -------------
#define GBM 64
#define GBN 64
#define GBK 16
__global__ void __launch_bounds__(256) embw_kernel(const float* __restrict__ emb,
                                                   const float* __restrict__ Wih,
                                                   const float* __restrict__ bih,
                                                   const float* __restrict__ hidden,
                                                   const float* __restrict__ stacks){
    __shared__ __align__(16) float As[GBK][68];
    __shared__ __align__(16) float Bs[GBK][68];
    int tid = threadIdx.x;

    // -------- merged init (blockIdx.y == 0 blocks only; 157*256 threads) ----
    if (blockIdx.y == 0){
        int i = blockIdx.x*256 + tid;
        int stride = gridDim.x*256;
        if (i == 0) g_bar = 0u;
        for (int u = i; u < BATCH*HID; u += stride){
            float v = hidden[u];
            g_hbh[0][u] = v;
            int b = u >> 9, h = u & 511;
            g_hT[0][h*BATCH + b] = v;
        }
        for (int u = i; u < STK_ELEMS; u += stride)
            g_st[0][u] = stacks[u];
    }

    int bm = blockIdx.x*GBM, bn = blockIdx.y*GBN;
    int tx = tid & 15, ty = tid >> 4;
    int lm = tid >> 2, lk = (tid & 3) * 4;

    u64 acc[4][2];
#pragma unroll
    for (int i = 0; i < 4; i++){ acc[i][0] = 0ull; acc[i][1] = 0ull; }

    bool aok = (bm + lm) < VOCAB;
    const float* arow = emb + (size_t)(bm + lm)*HID + lk;
    const float* brow = Wih + (size_t)(bn + lm)*HID + lk;

    for (int kt = 0; kt < HID; kt += GBK){
        float4 av = aok ? *(const float4*)(arow + kt) : make_float4(0.f,0.f,0.f,0.f);
        float4 bv = *(const float4*)(brow + kt);
        __syncthreads();
        As[lk+0][lm]=av.x; As[lk+1][lm]=av.y; As[lk+2][lm]=av.z; As[lk+3][lm]=av.w;
        Bs[lk+0][lm]=bv.x; Bs[lk+1][lm]=bv.y; Bs[lk+2][lm]=bv.z; Bs[lk+3][lm]=bv.w;
        __syncthreads();
#pragma unroll
        for (int k = 0; k < GBK; k++){
            float4 a = *(const float4*)&As[k][ty*4];
            ulonglong2 bb = *(const ulonglong2*)&Bs[k][tx*4];
            u64 s;
            s = pack2(a.x,a.x); fmax2(acc[0][0],s,bb.x); fmax2(acc[0][1],s,bb.y);
            s = pack2(a.y,a.y); fmax2(acc[1][0],s,bb.x); fmax2(acc[1][1],s,bb.y);
            s = pack2(a.z,a.z); fmax2(acc[2][0],s,bb.x); fmax2(acc[2][1],s,bb.y);
            s = pack2(a.w,a.w); fmax2(acc[3][0],s,bb.x); fmax2(acc[3][1],s,bb.y);
        }
    }
    int n0 = bn + tx*4;
    float bv0 = bih[n0+0], bv1 = bih[n0+1], bv2 = bih[n0+2], bv3 = bih[n0+3];
#pragma unroll
    for (int i = 0; i < 4; i++){
        int m = bm + ty*4 + i;
        if (m < VOCAB){
            float c0,c1,c2,c3;
            unpack2(acc[i][0], c0, c1); unpack2(acc[i][1], c2, c3);
            float4 res = make_float4(c0+bv0, c1+bv1, c2+bv2, c3+bv3);
            *(float4*)&g_EmbW[(size_t)m*TH + n0] = res;
        }
    }
}

// ---------------- grid barrier (105 blocks co-resident) -------------------
__device__ __forceinline__ void gridsync(unsigned &target){
    __syncthreads();
    target += NBLK;
    if (threadIdx.x == 0){
        __threadfence();
        atomicAdd(&g_bar, 1u);
        unsigned v;
        do {
            asm volatile("ld.volatile.global.u32 %0, [%1];" : "=r"(v) : "l"(&g_bar));
        } while (v < target);
        __threadfence();
    }
    __syncthreads();
}

// ---------------- persistent recurrence kernel ----------------------------
// dyn smem: Wsh u64[512*16] splatted (64KB) + Hsh f32[2][128*64] (64KB)
#define WSH_U64   (512*16)
#define HCHUNK    128
#define HSH_F32   (HCHUNK*BATCH)          // per buffer
#define RNN_SMEM  (WSH_U64*8 + 2*HSH_F32*4)

__global__ void __launch_bounds__(NTHR, 1) rnn_kernel(
    const int*   __restrict__ tokens,
    const float* __restrict__ Whh,  const float* __restrict__ Wact,
    const float* __restrict__ Wstk, const float* __restrict__ bhh,
    const float* __restrict__ bact, const float* __restrict__ bstk,
    const float* __restrict__ empty_e,
    float* __restrict__ out)
{
    extern __shared__ __align__(16) char smem[];
    u64*   Wsh = (u64*)smem;                         // [k(512)][16 j] splatted
    float* Hsh = (float*)(smem + WSH_U64*8);         // [2][128 k][64 b]

    const int tid = threadIdx.x, blk = blockIdx.x;
    const int j0  = blk * 16;
    const int gtid = blk*NTHR + tid;

    // load + splat this block's 16 weight columns (persist all steps)
    for (int idx = tid; idx < 512*16; idx += NTHR){
        int k = idx >> 4, jl = idx & 15;
        int j = j0 + jl;
        float w = 0.f;
        if      (j < ACT_OFF)                   w = Whh [(size_t)j*HID + k];
        else if (j < ACT_OFF+6)                 w = Wact[(size_t)(j-ACT_OFF)*HID + k];
        else if (j >= PUSH_OFF && j < JTOT)     w = Wstk[(size_t)(j-PUSH_OFF)*HID + k];
        Wsh[k*16 + jl] = pack2(w, w);
    }

    // consumer thread identity (tid < 128)
    const int bq = tid & 15;        // b-quad: covers b = bq*4 .. bq*4+3
    const int jg = (tid >> 4) & 7;  // j-pair: j = j0 + jg*2 (+0/+1)
    float bias0 = 0.f, bias1 = 0.f;
    {
        int j = j0 + jg*2;
#pragma unroll
        for (int m = 0; m < 2; m++){
            int jj = j + m;
            float bv = 0.f;
            if      (jj < ACT_OFF)               bv = bhh [jj];
            else if (jj < ACT_OFF+6)             bv = bact[jj-ACT_OFF];
            else if (jj >= PUSH_OFF && jj < JTOT)bv = bstk[jj-PUSH_OFF];
            if (m == 0) bias0 = bv; else bias1 = bv;
        }
    }

    float* outputs = out;
    float* out_h   = out + (size_t)T_STEPS*BATCH*HID;
    float* out_st  = out_h + BATCH*HID;

    unsigned target = 0;
    __syncthreads();   // Wsh ready

    for (int t = 0; t < T_STEPS; t++){
        const int cur = t & 1, nxt = cur ^ 1;

        // ============ Stage A: Gact = h_old @ Wf + bias ====================
        if (tid < 128){
            // ---- consumer warps 0-3 ----
            u64 acc00=0ull, acc10=0ull, acc01=0ull, acc11=0ull;
#pragma unroll 1
            for (int c = 0; c < 4; c++){
                const int buf = c & 1;
                barsync(1 + buf, NTHR);              // wait chunk ready
                const float* hp = Hsh + buf*HSH_F32 + bq*4;
                const u64*   wp = Wsh + (c*HCHUNK)*16 + jg*2;
#pragma unroll 8
                for (int kl = 0; kl < HCHUNK; kl++){
                    ulonglong2 h2 = *(const ulonglong2*)(hp + kl*64);
                    ulonglong2 w2 = *(const ulonglong2*)(wp + kl*16);
                    fmax2(acc00, h2.x, w2.x);
                    fmax2(acc10, h2.y, w2.x);
                    fmax2(acc01, h2.x, w2.y);
                    fmax2(acc11, h2.y, w2.y);
                }
                if (c < 2) bararrive(3 + buf, NTHR); // mark chunk free
            }
            // epilogue: 8 outputs -> Gact
            int b0 = bq*4, jA = j0 + jg*2;
            float v0, v1;
            unpack2(acc00, v0, v1);
            g_Gact[(b0+0)*JPAD + jA]   = v0 + bias0;
            g_Gact[(b0+1)*JPAD + jA]   = v1 + bias0;
            unpack2(acc10, v0, v1);
            g_Gact[(b0+2)*JPAD + jA]   = v0 + bias0;
            g_Gact[(b0+3)*JPAD + jA]   = v1 + bias0;
            unpack2(acc01, v0, v1);
            g_Gact[(b0+0)*JPAD + jA+1] = v0 + bias1;
            g_Gact[(b0+1)*JPAD + jA+1] = v1 + bias1;
            unpack2(acc11, v0, v1);
            g_Gact[(b0+2)*JPAD + jA+1] = v0 + bias1;
            g_Gact[(b0+3)*JPAD + jA+1] = v1 + bias1;
        } else {
            // ---- producer warps 4-7: stream h chunks L2 -> smem ----
            const int pt = tid - 128;
            const float4* src = (const float4*)g_hT[cur];
#pragma unroll 1
            for (int c = 0; c < 4; c++){
                const int buf = c & 1;
                if (c >= 2) barsync(3 + buf, NTHR);  // wait chunk free
                float4* dst = (float4*)(Hsh + buf*HSH_F32);
                const float4* s = src + c*(HSH_F32/4);
#pragma unroll
                for (int i = 0; i < 16; i++)
                    dst[i*128 + pt] = __ldcg(s + i*128 + pt);
                bararrive(1 + buf, NTHR);            // mark chunk ready
            }
        }

        gridsync(target);

        // ============ Stage B: gates + stack update (float4) ==============
        const int* tok_t = tokens + t*BATCH;
        for (int v = gtid; v < GATE4 + STK4; v += NTOT){
            if (v < GATE4){
                int b = v >> 7, i4 = v & 127;
                int tk = __ldg(tok_t + b);
                const float4* gi = (const float4*)(g_EmbW + (size_t)tk*TH);
                float4 gr = gi[i4], gz = gi[i4+128], gn = gi[i4+256];
                const float4* gh = (const float4*)(g_Gact + b*JPAD);
                float4 hr = __ldcg(gh+i4), hz = __ldcg(gh+i4+128), hn = __ldcg(gh+i4+256);
                float4 ho = __ldcg((const float4*)g_hbh[cur] + v);
                float4 nh;
                {
                    float r,z,n;
                    r = sigf(gr.x+hr.x); z = sigf(gz.x+hz.x);
                    n = tanhf(gn.x + r*hn.x); nh.x = (1.f-z)*n + z*ho.x;
                    r = sigf(gr.y+hr.y); z = sigf(gz.y+hz.y);
                    n = tanhf(gn.y + r*hn.y); nh.y = (1.f-z)*n + z*ho.y;
                    r = sigf(gr.z+hr.z); z = sigf(gz.z+hz.z);
                    n = tanhf(gn.z + r*hn.z); nh.z = (1.f-z)*n + z*ho.z;
                    r = sigf(gr.w+hr.w); z = sigf(gz.w+hz.w);
                    n = tanhf(gn.w + r*hn.w); nh.w = (1.f-z)*n + z*ho.w;
                }
                ((float4*)(outputs + (size_t)t*GATE_ELEMS))[v] = nh;
                ((float4*)g_hbh[nxt])[v] = nh;
                int ib = i4*4;
                g_hT[nxt][(ib+0)*BATCH + b] = nh.x;
                g_hT[nxt][(ib+1)*BATCH + b] = nh.y;
                g_hT[nxt][(ib+2)*BATCH + b] = nh.z;
                g_hT[nxt][(ib+3)*BATCH + b] = nh.w;
                if (t == T_STEPS-1) ((float4*)out_h)[v] = nh;
            } else {
                int v2 = v - GATE4;
                int e4 = v2 & 15;
                int i  = (v2 >> 4) & 31;
                int nn = (v2 >> 9) & 1;
                int bb = v2 >> 10;
                const float* ga = g_Gact + bb*JPAD + ACT_OFF + nn*3;
                float l0 = __ldcg(ga), l1 = __ldcg(ga+1), l2 = __ldcg(ga+2);
                float mx = fmaxf(l0, fmaxf(l1, l2));
                float e0 = __expf(l0-mx), e1 = __expf(l1-mx), e2 = __expf(l2-mx);
                float inv = __fdividef(1.f, e0+e1+e2);
                float p0 = e0*inv, p1 = e1*inv, p2 = e2*inv;
                float4 val;
                if (i == 0){
                    float4 pv = __ldcg((const float4*)(g_Gact + bb*JPAD + PUSH_OFF + nn*EDIM) + e4);
                    val.x = p0*tanhf(pv.x); val.y = p0*tanhf(pv.y);
                    val.z = p0*tanhf(pv.z); val.w = p0*tanhf(pv.w);
                } else if (i == SDEP-1){
                    val = __ldg((const float4*)empty_e + e4);
                } else {
                    const float4* sc = (const float4*)g_st[cur] + v2;
                    float4 dn = __ldcg(sc - 16), up = __ldcg(sc + 16), cu = __ldcg(sc);
                    val.x = p0*dn.x + p1*up.x + p2*cu.x;
                    val.y = p0*dn.y + p1*up.y + p2*cu.y;
                    val.z = p0*dn.z + p1*up.z + p2*cu.z;
                    val.w = p0*dn.w + p1*up.w + p2*cu.w;
                }
                ((float4*)g_st[nxt])[v2] = val;
                if (t == T_STEPS-1) ((float4*)out_st)[v2] = val;
            }
        }

        gridsync(target);
    }
}

// ---------------- launch --------------------------------------------------
extern "C" void kernel_launch(void* const* d_in, const int* in_sizes, int n_in,
                              void* d_out, int out_size){
    const int*   tokens  = (const int*)  d_in[0];
    const float* hidden  = (const float*)d_in[1];
    const float* stacks  = (const float*)d_in[2];
    const float* emb     = (const float*)d_in[3];
    const float* Wih     = (const float*)d_in[4];
    const float* Whh     = (const float*)d_in[5];
    const float* bih     = (const float*)d_in[6];
    const float* bhh     = (const float*)d_in[7];
    const float* Wact    = (const float*)d_in[8];
    const float* bact    = (const float*)d_in[9];
    const float* Wstk    = (const float*)d_in[10];
    const float* bstk    = (const float*)d_in[11];
    const float* empty_e = (const float*)d_in[12];
    float* out = (float*)d_out;

    dim3 ggrid((VOCAB + GBM - 1)/GBM, TH/GBN);   // 157 x 24
    embw_kernel<<<ggrid, 256>>>(emb, Wih, bih, hidden, stacks);

    cudaFuncSetAttribute(rnn_kernel, cudaFuncAttributeMaxDynamicSharedMemorySize, RNN_SMEM);
    rnn_kernel<<<NBLK, NTHR, RNN_SMEM>>>(tokens, Whh, Wact, Wstk,
                                         bhh, bact, bstk, empty_e, out);
}

// round 6
// speedup vs baseline: 1.7189x; 1.2291x over previous
#include <cuda_runtime.h>
#include <math.h>
#include <stdint.h>

// ---------------- problem constants ----------------
#define T_STEPS 512
#define BATCH   64
#define HID     512
#define VOCAB   10000
#define TH      1536
#define NSTK    2
#define SDEP    32
#define EDIM    64
#define NBLK    140           // 128 gate blocks + 12 extras blocks
#define NGATE   128
#define NTHR    256
#define NTOT    (NBLK*NTHR)   // 35840
#define GATE_ELEMS (BATCH*HID)            // 32768
#define STK_ELEMS  (BATCH*NSTK*SDEP*EDIM) // 262144
#define STK4  (STK_ELEMS/4)               // 65536
#define XW    160             // GactX row stride (cols: 0-5 act, 8-135 push)

// ---------------- scratch (device globals) ----------------
__device__ float g_EmbW[VOCAB*TH];          // emb @ W_ih^T + b_ih
__device__ float g_hT [2][HID*BATCH];       // h, [i][b]
__device__ float g_GactX[2][BATCH*XW];      // act/push pre-acts, double buffered
__device__ float g_st[2][STK_ELEMS];        // stacks double buffer
__device__ unsigned g_bar;                  // grid barrier counter

typedef unsigned long long u64;

__device__ __forceinline__ u64 pack2(float x, float y){
    u64 r; asm("mov.b64 %0, {%1,%2};" : "=l"(r) : "f"(x), "f"(y)); return r;
}
__device__ __forceinline__ void unpack2(u64 v, float &x, float &y){
    asm("mov.b64 {%0,%1}, %2;" : "=f"(x), "=f"(y) : "l"(v));
}
__device__ __forceinline__ void fmax2(u64 &d, u64 a, u64 b){
    asm("fma.rn.f32x2 %0, %1, %2, %0;" : "+l"(d) : "l"(a), "l"(b));
}
__device__ __forceinline__ float sigf(float x){
    return __fdividef(1.f, 1.f + __expf(-x));
}
__device__ __forceinline__ void barsync(int id, int cnt){
    asm volatile("bar.sync %0, %1;" :: "r"(id), "r"(cnt) : "memory");
}
__device__ __forceinline__ void bararrive(int id, int cnt){
    asm volatile("bar.arrive %0, %1;" :: "r"(id), "r"(cnt) : "memory");
}

// ---------------- EmbW = emb @ W_ih^T + b_ih  (+ merged init) -------------
#define GBM 64
#define GBN 64
#define GBK 16
__global__ void __launch_bounds__(256) embw_kernel(const float* __restrict__ emb,
                                                   const float* __restrict__ Wih,
                                                   const float* __restrict__ bih,
                                                   const float* __restrict__ hidden,
                                                   const float* __restrict__ stacks){
    __shared__ __align__(16) float As[GBK][68];
    __shared__ __align__(16) float Bs[GBK][68];
    int tid = threadIdx.x;

    if (blockIdx.y == 0){
        int i = blockIdx.x*256 + tid;
        int stride = gridDim.x*256;
        if (i == 0) g_bar = 0u;
        for (int u = i; u < BATCH*HID; u += stride){
            float v = hidden[u];
            int b = u >> 9, h = u & 511;
            g_hT[0][h*BATCH + b] = v;
        }
        for (int u = i; u < STK_ELEMS; u += stride)
            g_st[0][u] = stacks[u];
    }

    int bm = blockIdx.x*GBM, bn = blockIdx.y*GBN;
    int tx = tid & 15, ty = tid >> 4;
    int lm = tid >> 2, lk = (tid & 3) * 4;

    u64 acc[4][2];
#pragma unroll
    for (int i = 0; i < 4; i++){ acc[i][0] = 0ull; acc[i][1] = 0ull; }

    bool aok = (bm + lm) < VOCAB;
    const float* arow = emb + (size_t)(bm + lm)*HID + lk;
    const float* brow = Wih + (size_t)(bn + lm)*HID + lk;

    for (int kt = 0; kt < HID; kt += GBK){
        float4 av = aok ? *(const float4*)(arow + kt) : make_float4(0.f,0.f,0.f,0.f);
        float4 bv = *(const float4*)(brow + kt);
        __syncthreads();
        As[lk+0][lm]=av.x; As[lk+1][lm]=av.y; As[lk+2][lm]=av.z; As[lk+3][lm]=av.w;
        Bs[lk+0][lm]=bv.x; Bs[lk+1][lm]=bv.y; Bs[lk+2][lm]=bv.z; Bs[lk+3][lm]=bv.w;
        __syncthreads();
#pragma unroll
        for (int k = 0; k < GBK; k++){
            float4 a = *(const float4*)&As[k][ty*4];
            ulonglong2 bb = *(const ulonglong2*)&Bs[k][tx*4];
            u64 s;
            s = pack2(a.x,a.x); fmax2(acc[0][0],s,bb.x); fmax2(acc[0][1],s,bb.y);
            s = pack2(a.y,a.y); fmax2(acc[1][0],s,bb.x); fmax2(acc[1][1],s,bb.y);
            s = pack2(a.z,a.z); fmax2(acc[2][0],s,bb.x); fmax2(acc[2][1],s,bb.y);
            s = pack2(a.w,a.w); fmax2(acc[3][0],s,bb.x); fmax2(acc[3][1],s,bb.y);
        }
    }
    int n0 = bn + tx*4;
    float bv0 = bih[n0+0], bv1 = bih[n0+1], bv2 = bih[n0+2], bv3 = bih[n0+3];
#pragma unroll
    for (int i = 0; i < 4; i++){
        int m = bm + ty*4 + i;
        if (m < VOCAB){
            float c0,c1,c2,c3;
            unpack2(acc[i][0], c0, c1); unpack2(acc[i][1], c2, c3);
            float4 res = make_float4(c0+bv0, c1+bv1, c2+bv2, c3+bv3);
            *(float4*)&g_EmbW[(size_t)m*TH + n0] = res;
        }
    }
}

// ---------------- grid barrier (acquire/release, 140 blocks) --------------
__device__ __forceinline__ void gridsync(unsigned &target){
    __syncthreads();
    target += NBLK;
    if (threadIdx.x == 0){
        asm volatile("red.release.gpu.global.add.u32 [%0], 1;" :: "l"(&g_bar) : "memory");
        unsigned v;
        do {
            asm volatile("ld.acquire.gpu.global.u32 %0, [%1];" : "=r"(v) : "l"(&g_bar) : "memory");
        } while (v < target);
    }
    __syncthreads();
}

// ---------------- persistent recurrence kernel ----------------------------
// dyn smem: Wsh u64[512*16] splatted (64KB) + Hsh f32[2][128*64] (64KB)
// Gsh (16x64 f32, 4KB) aliases the start of Hsh after chunks consumed.
#define WSH_U64   (512*16)
#define HCHUNK    128
#define HSH_F32   (HCHUNK*BATCH)
#define RNN_SMEM  (WSH_U64*8 + 2*HSH_F32*4)

__global__ void __launch_bounds__(NTHR, 1) rnn_kernel(
    const int*   __restrict__ tokens,
    const float* __restrict__ Whh,  const float* __restrict__ Wact,
    const float* __restrict__ Wstk, const float* __restrict__ bhh,
    const float* __restrict__ bact, const float* __restrict__ bstk,
    const float* __restrict__ empty_e,
    float* __restrict__ out)
{
    extern __shared__ __align__(16) char smem[];
    u64*   Wsh = (u64*)smem;                         // [k(512)][16 j] splatted
    float* Hsh = (float*)(smem + WSH_U64*8);         // [2][128 k][64 b]
    float* Gsh = Hsh;                                // [16 j][64 b] (aliased)

    const int tid = threadIdx.x, blk = blockIdx.x;
    const int gtid = blk*NTHR + tid;
    const bool is_gate = (blk < NGATE);

    // ---- load + splat this block's 16 weight columns (persist all steps) ----
    // gate block: jl<12 -> Whh row (jl>>2)*512 + blk*4 + (jl&3)
    // extras block: ee=(blk-128)*12+jl; ee<6 -> Wact[ee]; 8<=ee<136 -> Wstk[ee-8]
    for (int idx = tid; idx < 512*16; idx += NTHR){
        int k = idx >> 4, jl = idx & 15;
        float w = 0.f;
        if (is_gate){
            if (jl < 12){
                int row = (jl >> 2)*HID + blk*4 + (jl & 3);
                w = Whh[(size_t)row*HID + k];
            }
        } else {
            if (jl < 12){
                int ee = (blk - NGATE)*12 + jl;
                if      (ee < 6)               w = Wact[(size_t)ee*HID + k];
                else if (ee >= 8 && ee < 136)  w = Wstk[(size_t)(ee-8)*HID + k];
            }
        }
        Wsh[k*16 + jl] = pack2(w, w);
    }

    // consumer identity (tid < 128): bq in 0..15 (4 b each), jg in 0..7 (2 j each)
    const int bq = tid & 15;
    const int jg = (tid >> 4) & 7;
    float bias0 = 0.f, bias1 = 0.f;
#pragma unroll
    for (int m2 = 0; m2 < 2; m2++){
        int jl = jg*2 + m2;
        float bv = 0.f;
        if (is_gate){
            if (jl < 12) bv = bhh[(jl >> 2)*HID + blk*4 + (jl & 3)];
        } else {
            if (jl < 12){
                int ee = (blk - NGATE)*12 + jl;
                if      (ee < 6)              bv = bact[ee];
                else if (ee >= 8 && ee < 136) bv = bstk[ee-8];
            }
        }
        if (m2 == 0) bias0 = bv; else bias1 = bv;
    }

    float* outputs = out;
    float* out_h   = out + (size_t)T_STEPS*BATCH*HID;
    float* out_st  = out_h + BATCH*HID;

    unsigned target = 0;
    __syncthreads();   // Wsh ready

    for (int t = 0; t < T_STEPS; t++){
        const int cur = t & 1, nxt = cur ^ 1;

        // ============ Stage A: 16-col GEMM vs h_old ========================
        if (tid < 128){
            u64 acc00=0ull, acc10=0ull, acc01=0ull, acc11=0ull;
#pragma unroll 1
            for (int c = 0; c < 4; c++){
                const int buf = c & 1;
                barsync(1 + buf, NTHR);
                const float* hp = Hsh + buf*HSH_F32 + bq*4;
                const u64*   wp = Wsh + (c*HCHUNK)*16 + jg*2;
#pragma unroll 8
                for (int kl = 0; kl < HCHUNK; kl++){
                    ulonglong2 h2 = *(const ulonglong2*)(hp + kl*64);
                    ulonglong2 w2 = *(const ulonglong2*)(wp + kl*16);
                    fmax2(acc00, h2.x, w2.x);
                    fmax2(acc10, h2.y, w2.x);
                    fmax2(acc01, h2.x, w2.y);
                    fmax2(acc11, h2.y, w2.y);
                }
                if (c < 2) bararrive(3 + buf, NTHR);
            }
            // write pre-acts (+bias) to Gsh[jl][b]
            int b0 = bq*4, jA = jg*2;
            float v0, v1;
            unpack2(acc00, v0, v1);
            Gsh[jA*64     + b0+0] = v0 + bias0;
            Gsh[jA*64     + b0+1] = v1 + bias0;
            unpack2(acc10, v0, v1);
            Gsh[jA*64     + b0+2] = v0 + bias0;
            Gsh[jA*64     + b0+3] = v1 + bias0;
            unpack2(acc01, v0, v1);
            Gsh[(jA+1)*64 + b0+0] = v0 + bias1;
            Gsh[(jA+1)*64 + b0+1] = v1 + bias1;
            unpack2(acc11, v0, v1);
            Gsh[(jA+1)*64 + b0+2] = v0 + bias1;
            Gsh[(jA+1)*64 + b0+3] = v1 + bias1;
        } else {
            // producer warps: stream h_old chunks L2 -> smem
            const int pt = tid - 128;
            const float4* src = (const float4*)g_hT[cur];
#pragma unroll 1
            for (int c = 0; c < 4; c++){
                const int buf = c & 1;
                if (c >= 2) barsync(3 + buf, NTHR);
                float4* dst = (float4*)(Hsh + buf*HSH_F32);
                const float4* s = src + c*(HSH_F32/4);
#pragma unroll
                for (int i = 0; i < 16; i++)
                    dst[i*128 + pt] = __ldcg(s + i*128 + pt);
                bararrive(1 + buf, NTHR);
            }
        }
        __syncthreads();   // Gsh complete (and chunk buffers retired)

        // ============ In-block epilogue ====================================
        if (is_gate){
            // gates: each thread handles one (b, i_m): m = tid&3, b = (tid>>2)
            int m = tid & 3, b = tid >> 2;      // b in 0..63
            int i = blk*4 + m;
            int tk = __ldg(tokens + t*BATCH + b);
            const float* gi = g_EmbW + (size_t)tk*TH + i;
            float gir = __ldg(gi), giz = __ldg(gi+512), gin = __ldg(gi+1024);
            float ghr = Gsh[m*64 + b], ghz = Gsh[(m+4)*64 + b], ghn = Gsh[(m+8)*64 + b];
            float hold = __ldcg(&g_hT[cur][i*BATCH + b]);
            float r = sigf(gir + ghr);
            float z = sigf(giz + ghz);
            float n = tanhf(gin + r*ghn);
            float nh = (1.f - z)*n + z*hold;
            outputs[(size_t)t*GATE_ELEMS + b*HID + i] = nh;
            g_hT[nxt][i*BATCH + b] = nh;
            if (t == T_STEPS-1) out_h[b*HID + i] = nh;
        } else {
            // extras: copy 12 cols to global (double buffered)
            float* gx = g_GactX[cur];
            for (int u = tid; u < 12*64; u += NTHR){
                int jl = u >> 6, b = u & 63;
                int ee = (blk - NGATE)*12 + jl;
                gx[b*XW + ee] = Gsh[jl*64 + b];
            }
        }

        gridsync(target);

        // ============ Stack update (float4) ================================
        for (int v2 = gtid; v2 < STK4; v2 += NTOT){
            int e4 = v2 & 15;
            int i  = (v2 >> 4) & 31;
            int nn = (v2 >> 9) & 1;
            int bb = v2 >> 10;
            const float* ga = g_GactX[cur] + bb*XW + nn*3;
            float l0 = __ldcg(ga), l1 = __ldcg(ga+1), l2 = __ldcg(ga+2);
            float mx = fmaxf(l0, fmaxf(l1, l2));
            float e0 = __expf(l0-mx), e1 = __expf(l1-mx), e2 = __expf(l2-mx);
            float inv = __fdividef(1.f, e0+e1+e2);
            float p0 = e0*inv, p1 = e1*inv, p2 = e2*inv;
            float4 val;
            if (i == 0){
                float4 pv = __ldcg((const float4*)(g_GactX[cur] + bb*XW + 8 + nn*EDIM) + e4);
                val.x = p0*tanhf(pv.x); val.y = p0*tanhf(pv.y);
                val.z = p0*tanhf(pv.z); val.w = p0*tanhf(pv.w);
            } else if (i == SDEP-1){
                val = __ldg((const float4*)empty_e + e4);
            } else {
                const float4* sc = (const float4*)g_st[cur] + v2;
                float4 dn = __ldcg(sc - 16), up = __ldcg(sc + 16), cu = __ldcg(sc);
                val.x = p0*dn.x + p1*up.x + p2*cu.x;
                val.y = p0*dn.y + p1*up.y + p2*cu.y;
                val.z = p0*dn.z + p1*up.z + p2*cu.z;
                val.w = p0*dn.w + p1*up.w + p2*cu.w;
            }
            ((float4*)g_st[nxt])[v2] = val;
            if (t == T_STEPS-1) ((float4*)out_st)[v2] = val;
        }
    }
}

// ---------------- launch --------------------------------------------------
extern "C" void kernel_launch(void* const* d_in, const int* in_sizes, int n_in,
                              void* d_out, int out_size){
    const int*   tokens  = (const int*)  d_in[0];
    const float* hidden  = (const float*)d_in[1];
    const float* stacks  = (const float*)d_in[2];
    const float* emb     = (const float*)d_in[3];
    const float* Wih     = (const float*)d_in[4];
    const float* Whh     = (const float*)d_in[5];
    const float* bih     = (const float*)d_in[6];
    const float* bhh     = (const float*)d_in[7];
    const float* Wact    = (const float*)d_in[8];
    const float* bact    = (const float*)d_in[9];
    const float* Wstk    = (const float*)d_in[10];
    const float* bstk    = (const float*)d_in[11];
    const float* empty_e = (const float*)d_in[12];
    float* out = (float*)d_out;

    dim3 ggrid((VOCAB + GBM - 1)/GBM, TH/GBN);   // 157 x 24
    embw_kernel<<<ggrid, 256>>>(emb, Wih, bih, hidden, stacks);

    cudaFuncSetAttribute(rnn_kernel, cudaFuncAttributeMaxDynamicSharedMemorySize, RNN_SMEM);
    rnn_kernel<<<NBLK, NTHR, RNN_SMEM>>>(tokens, Whh, Wact, Wstk,
                                         bhh, bact, bstk, empty_e, out);
}

// round 9
// speedup vs baseline: 2.6772x; 1.5575x over previous
#include <cuda_runtime.h>
#include <math.h>
#include <stdint.h>

// ---------------- problem constants ----------------
#define T_STEPS 512
#define BATCH   64
#define HID     512
#define VOCAB   10000
#define TH      1536
#define SDEP    32
#define EDIM    64
#define NGATE   103           // gate GEMM blocks, 5 i-triples each (515>=512)
#define NEXTRA  9             // extras GEMM blocks, 16 cols each (144>=134)
#define NGEMM   (NGATE+NEXTRA)// 112
#define NSTACK  36
#define NBLK    (NGEMM+NSTACK)// 148 = #SMs
#define NTHR    256
#define XW      160           // GactX row stride: cols 0-5 act, 8-135 push
#define GATE_ELEMS (BATCH*HID)
#define STK_ELEMS  (BATCH*2*SDEP*EDIM)    // 262144
#define STK4  (STK_ELEMS/4)

// ---------------- scratch (device globals) ----------------
__device__ float g_EmbW[VOCAB*TH];
__device__ float g_hT[2][HID*BATCH];      // h, [k][b] (b contiguous)
__device__ float g_GactX[2][BATCH*XW];    // act/push pre-acts
__device__ float g_st[2][STK_ELEMS];
__device__ unsigned g_bar;

typedef unsigned long long u64;

__device__ __forceinline__ u64 pack2(float x, float y){
    u64 r; asm("mov.b64 %0, {%1,%2};" : "=l"(r) : "f"(x), "f"(y)); return r;
}
__device__ __forceinline__ void unpack2(u64 v, float &x, float &y){
    asm("mov.b64 {%0,%1}, %2;" : "=f"(x), "=f"(y) : "l"(v));
}
__device__ __forceinline__ void fmax2(u64 &d, u64 a, u64 b){
    asm("fma.rn.f32x2 %0, %1, %2, %0;" : "+l"(d) : "l"(a), "l"(b));
}
__device__ __forceinline__ void add2(u64 &d, u64 a){
    asm("add.rn.f32x2 %0, %0, %1;" : "+l"(d) : "l"(a));
}
__device__ __forceinline__ float sigf(float x){
    return __fdividef(1.f, 1.f + __expf(-x));
}
__device__ __forceinline__ float tanhf_fast(float x){
    float e = __expf(2.f*x);
    return 1.f - __fdividef(2.f, e + 1.f);
}

// ---------------- EmbW = emb @ W_ih^T + b_ih  (+ merged init) -------------
#define GBM 64
#define GBN 64
#define GBK 16
__global__ void __launch_bounds__(256) embw_kernel(const float* __restrict__ emb,
                                                   const float* __restrict__ Wih,
                                                   const float* __restrict__ bih,
                                                   const float* __restrict__ hidden,
                                                   const float* __restrict__ stacks){
    __shared__ __align__(16) float As[GBK][68];
    __shared__ __align__(16) float Bs[GBK][68];
    int tid = threadIdx.x;

    if (blockIdx.y == 0){
        int i = blockIdx.x*256 + tid;
        int stride = gridDim.x*256;
        if (i == 0) g_bar = 0u;
        for (int u = i; u < BATCH*HID; u += stride){
            float v = hidden[u];
            int b = u >> 9, h = u & 511;
            g_hT[0][h*BATCH + b] = v;
        }
        for (int u = i; u < STK_ELEMS; u += stride)
            g_st[0][u] = stacks[u];
    }

    int bm = blockIdx.x*GBM, bn = blockIdx.y*GBN;
    int tx = tid & 15, ty = tid >> 4;
    int lm = tid >> 2, lk = (tid & 3) * 4;

    u64 acc[4][2];
#pragma unroll
    for (int i = 0; i < 4; i++){ acc[i][0] = 0ull; acc[i][1] = 0ull; }

    bool aok = (bm + lm) < VOCAB;
    const float* arow = emb + (size_t)(bm + lm)*HID + lk;
    const float* brow = Wih + (size_t)(bn + lm)*HID + lk;

    for (int kt = 0; kt < HID; kt += GBK){
        float4 av = aok ? *(const float4*)(arow + kt) : make_float4(0.f,0.f,0.f,0.f);
        float4 bv = *(const float4*)(brow + kt);
        __syncthreads();
        As[lk+0][lm]=av.x; As[lk+1][lm]=av.y; As[lk+2][lm]=av.z; As[lk+3][lm]=av.w;
        Bs[lk+0][lm]=bv.x; Bs[lk+1][lm]=bv.y; Bs[lk+2][lm]=bv.z; Bs[lk+3][lm]=bv.w;
        __syncthreads();
#pragma unroll
        for (int k = 0; k < GBK; k++){
            float4 a = *(const float4*)&As[k][ty*4];
            ulonglong2 bb = *(const ulonglong2*)&Bs[k][tx*4];
            u64 s;
            s = pack2(a.x,a.x); fmax2(acc[0][0],s,bb.x); fmax2(acc[0][1],s,bb.y);
            s = pack2(a.y,a.y); fmax2(acc[1][0],s,bb.x); fmax2(acc[1][1],s,bb.y);
            s = pack2(a.z,a.z); fmax2(acc[2][0],s,bb.x); fmax2(acc[2][1],s,bb.y);
            s = pack2(a.w,a.w); fmax2(acc[3][0],s,bb.x); fmax2(acc[3][1],s,bb.y);
        }
    }
    int n0 = bn + tx*4;
    float bv0 = bih[n0+0], bv1 = bih[n0+1], bv2 = bih[n0+2], bv3 = bih[n0+3];
#pragma unroll
    for (int i = 0; i < 4; i++){
        int m = bm + ty*4 + i;
        if (m < VOCAB){
            float c0,c1,c2,c3;
            unpack2(acc[i][0], c0, c1); unpack2(acc[i][1], c2, c3);
            float4 res = make_float4(c0+bv0, c1+bv1, c2+bv2, c3+bv3);
            *(float4*)&g_EmbW[(size_t)m*TH + n0] = res;
        }
    }
}

// ---------------- grid barrier --------------------------------------------
__device__ __forceinline__ void gridsync(unsigned &target){
    __syncthreads();
    target += NBLK;
    if (threadIdx.x == 0){
        asm volatile("red.release.gpu.global.add.u32 [%0], 1;" :: "l"(&g_bar) : "memory");
        unsigned v;
        do {
            asm volatile("ld.acquire.gpu.global.u32 %0, [%1];" : "=r"(v) : "l"(&g_bar) : "memory");
        } while (v < target);
    }
    __syncthreads();
}

// ---------------- smem layout (dyn, 128KB to force 1 CTA/SM) --------------
#define SM_W     0            // Wsh: [k(512)][16j] f32 = 32KB
#define SM_RBUF  32768        // partials: [8 warps][16j][32 bpair] u64 = 32KB
#define SM_GSH   65536        // Gsh: [16j][64b] f32 = 4KB
#define SM_BIAS  69632        // bias_sm[16]
#define RNN_SMEM 131072

// ---------------- persistent recurrence kernel -----------------------------
__global__ void __launch_bounds__(NTHR, 1) rnn_kernel(
    const int*   __restrict__ tokens,
    const float* __restrict__ Whh,  const float* __restrict__ Wact,
    const float* __restrict__ Wstk, const float* __restrict__ bhh,
    const float* __restrict__ bact, const float* __restrict__ bstk,
    const float* __restrict__ empty_e,
    float* __restrict__ out)
{
    extern __shared__ __align__(16) char smem[];
    float* Wsh     = (float*)(smem + SM_W);
    u64*   Rbuf    = (u64*)  (smem + SM_RBUF);
    float* Gsh     = (float*)(smem + SM_GSH);
    float* bias_sm = (float*)(smem + SM_BIAS);

    const int tid = threadIdx.x, q = blockIdx.x;
    const int wid = tid >> 5, lane = tid & 31;

    float* outputs = out;
    float* out_h   = out + (size_t)T_STEPS*BATCH*HID;
    float* out_st  = out_h + BATCH*HID;

    unsigned target = 0;

    if (q >= NGEMM){
        // ================== stack blocks (36) ============================
        const int sblk = q - NGEMM;
        for (int t = 0; t < T_STEPS; t++){
            gridsync(target);
            const int cur = t & 1, nxt = cur ^ 1;
            const float* gx = g_GactX[cur];
            for (int v2 = sblk*NTHR + tid; v2 < STK4; v2 += NSTACK*NTHR){
                int e4 = v2 & 15;
                int i  = (v2 >> 4) & 31;
                int nn = (v2 >> 9) & 1;
                int bb = v2 >> 10;
                const float* ga = gx + bb*XW + nn*3;
                float l0 = __ldcg(ga), l1 = __ldcg(ga+1), l2 = __ldcg(ga+2);
                float mx = fmaxf(l0, fmaxf(l1, l2));
                float e0 = __expf(l0-mx), e1 = __expf(l1-mx), e2 = __expf(l2-mx);
                float inv = __fdividef(1.f, e0+e1+e2);
                float p0 = e0*inv, p1 = e1*inv, p2 = e2*inv;
                float4 val;
                if (i == 0){
                    float4 pv = __ldcg((const float4*)(gx + bb*XW + 8 + nn*EDIM) + e4);
                    val.x = p0*tanhf_fast(pv.x); val.y = p0*tanhf_fast(pv.y);
                    val.z = p0*tanhf_fast(pv.z); val.w = p0*tanhf_fast(pv.w);
                } else if (i == SDEP-1){
                    val = __ldg((const float4*)empty_e + e4);
                } else {
                    const float4* sc = (const float4*)g_st[cur] + v2;
                    float4 dn = __ldcg(sc - 16), up = __ldcg(sc + 16), cu = __ldcg(sc);
                    val.x = p0*dn.x + p1*up.x + p2*cu.x;
                    val.y = p0*dn.y + p1*up.y + p2*cu.y;
                    val.z = p0*dn.z + p1*up.z + p2*cu.z;
                    val.w = p0*dn.w + p1*up.w + p2*cu.w;
                }
                ((float4*)g_st[nxt])[v2] = val;
                if (t == T_STEPS-1) ((float4*)out_st)[v2] = val;
            }
        }
        return;
    }

    // ================== GEMM blocks (112) ================================
    const bool is_gate = (q < NGATE);

    // W cols for this block: gate: jl = mm*3+cc (5 i-triples, col 15 pad);
    // extras: ee = (q-NGATE)*16 + jl
    for (int idx = tid; idx < 512*16; idx += NTHR){
        int k = idx >> 4, jl = idx & 15;
        float w = 0.f;
        if (is_gate){
            if (jl < 15){
                int mm = jl/3, cc = jl - mm*3;
                int i = q*5 + mm;
                if (i < HID) w = Whh[(size_t)(cc*HID + i)*HID + k];
            }
        } else {
            int ee = (q - NGATE)*16 + jl;
            if      (ee < 6)               w = Wact[(size_t)ee*HID + k];
            else if (ee >= 8 && ee < 136)  w = Wstk[(size_t)(ee-8)*HID + k];
        }
        Wsh[k*16 + jl] = w;
    }
    if (tid < 16){
        int jl = tid;
        float bv = 0.f;
        if (is_gate){
            if (jl < 15){
                int mm = jl/3, cc = jl - mm*3;
                int i = q*5 + mm;
                if (i < HID) bv = bhh[cc*HID + i];
            }
        } else {
            int ee = (q - NGATE)*16 + jl;
            if      (ee < 6)               bv = bact[ee];
            else if (ee >= 8 && ee < 136)  bv = bstk[ee-8];
        }
        bias_sm[jl] = bv;
    }
    __syncthreads();

    for (int t = 0; t < T_STEPS; t++){
        const int cur = t & 1, nxt = cur ^ 1;

        // ---- Stage A: k-sliced GEMM; h pairs direct from L2 --------------
        {
            const u64* hp = (const u64*)(g_hT[cur]) + lane;   // + k*32
            const float4* w4 = (const float4*)Wsh;            // + k*4
            u64 acc[16];
#pragma unroll
            for (int j = 0; j < 16; j++) acc[j] = 0ull;
            const int k0 = wid*64;
#pragma unroll 8
            for (int k = k0; k < k0 + 64; k++){
                u64 h2 = __ldcg(hp + k*32);
                float4 a = w4[k*4+0];
                float4 b = w4[k*4+1];
                float4 c = w4[k*4+2];
                float4 d = w4[k*4+3];
                fmax2(acc[ 0], h2, pack2(a.x,a.x));
                fmax2(acc[ 1], h2, pack2(a.y,a.y));
                fmax2(acc[ 2], h2, pack2(a.z,a.z));
                fmax2(acc[ 3], h2, pack2(a.w,a.w));
                fmax2(acc[ 4], h2, pack2(b.x,b.x));
                fmax2(acc[ 5], h2, pack2(b.y,b.y));
                fmax2(acc[ 6], h2, pack2(b.z,b.z));
                fmax2(acc[ 7], h2, pack2(b.w,b.w));
                fmax2(acc[ 8], h2, pack2(c.x,c.x));
                fmax2(acc[ 9], h2, pack2(c.y,c.y));
                fmax2(acc[10], h2, pack2(c.z,c.z));
                fmax2(acc[11], h2, pack2(c.w,c.w));
                fmax2(acc[12], h2, pack2(d.x,d.x));
                fmax2(acc[13], h2, pack2(d.y,d.y));
                fmax2(acc[14], h2, pack2(d.z,d.z));
                fmax2(acc[15], h2, pack2(d.w,d.w));
            }
            u64* rb = Rbuf + wid*512 + lane;
#pragma unroll
            for (int j = 0; j < 16; j++) rb[j*32] = acc[j];
        }
        __syncthreads();

        // ---- reduce 8 warp-partials, add bias -> Gsh[j][b] ---------------
        for (int s = tid; s < 512; s += NTHR){
            int j = s >> 5, l2 = s & 31;
            u64 sum = Rbuf[s];
#pragma unroll
            for (int w2 = 1; w2 < 8; w2++) add2(sum, Rbuf[w2*512 + s]);
            float x, y; unpack2(sum, x, y);
            float bb = bias_sm[j];
            Gsh[j*64 + 2*l2]     = x + bb;
            Gsh[j*64 + 2*l2 + 1] = y + bb;
        }
        __syncthreads();

        // ---- epilogue ----------------------------------------------------
        if (is_gate){
            const int* tok_t = tokens + t*BATCH;
            for (int u = tid; u < 5*64; u += NTHR){
                int mm = u >> 6, b = u & 63;
                int i = q*5 + mm;
                if (i < HID){
                    float pr = Gsh[(mm*3+0)*64 + b];
                    float pz = Gsh[(mm*3+1)*64 + b];
                    float pn = Gsh[(mm*3+2)*64 + b];
                    int tk = __ldg(tok_t + b);
                    const float* gi = g_EmbW + (size_t)tk*TH + i;
                    float r = sigf(__ldg(gi)        + pr);
                    float z = sigf(__ldg(gi+HID)    + pz);
                    float n = tanhf_fast(__ldg(gi+2*HID) + r*pn);
                    float hold = __ldcg(&g_hT[cur][i*BATCH + b]);
                    float nh = (1.f - z)*n + z*hold;
                    outputs[(size_t)t*GATE_ELEMS + b*HID + i] = nh;
                    g_hT[nxt][i*BATCH + b] = nh;
                    if (t == T_STEPS-1) out_h[b*HID + i] = nh;
                }
            }
        } else {
            float* gx = g_GactX[cur];
            int ex = q - NGATE;
            for (int u = tid; u < 16*64; u += NTHR){
                int jl = u >> 6, b = u & 63;
                int ee = ex*16 + jl;
                if (ee < 136 && (ee < 6 || ee >= 8)){
                    gx[b*XW + ee] = Gsh[jl*64 + b];
                }
            }
        }

        gridsync(target);
    }
}

// ---------------- launch --------------------------------------------------
extern "C" void kernel_launch(void* const* d_in, const int* in_sizes, int n_in,
                              void* d_out, int out_size){
    const int*   tokens  = (const int*)  d_in[0];
    const float* hidden  = (const float*)d_in[1];
    const float* stacks  = (const float*)d_in[2];
    const float* emb     = (const float*)d_in[3];
    const float* Wih     = (const float*)d_in[4];
    const float* Whh     = (const float*)d_in[5];
    const float* bih     = (const float*)d_in[6];
    const float* bhh     = (const float*)d_in[7];
    const float* Wact    = (const float*)d_in[8];
    const float* bact    = (const float*)d_in[9];
    const float* Wstk    = (const float*)d_in[10];
    const float* bstk    = (const float*)d_in[11];
    const float* empty_e = (const float*)d_in[12];
    float* out = (float*)d_out;

    dim3 ggrid((VOCAB + GBM - 1)/GBM, TH/GBN);   // 157 x 24
    embw_kernel<<<ggrid, 256>>>(emb, Wih, bih, hidden, stacks);

    cudaFuncSetAttribute(rnn_kernel, cudaFuncAttributeMaxDynamicSharedMemorySize, RNN_SMEM);
    rnn_kernel<<<NBLK, NTHR, RNN_SMEM>>>(tokens, Whh, Wact, Wstk,
                                         bhh, bact, bstk, empty_e, out);
}